// round 7
// baseline (speedup 1.0000x reference)
#include <cuda_runtime.h>
#include <math.h>

// FullPairwise neighbor list: M=8 molecules, N=1024 atoms, cutoff 5.2.
// Output (float32 buffer): [2, P] flat atom indices written as floats
// (row 0: i's, row 1: j's), pairs ordered lexicographically by
// (molecule, i, j); trailing elements (incl. the zeros(3) output) zeroed.
//
// Pipeline:
//  1) enum:   128row x 32col tiles -> one hit-bitmask uint32 per (row,chunk)
//  2) rowsum: warp-per-row popc reduce -> per-row pair counts
//  3) scan:   1-block shfl scan over 8192 row counts (row order == output order)
//  4) emit:   warp-per-row, lane=chunk, popc prefix -> write pairs + tail zero

#define NMOL 8
#define NATM 1024
#define NROWS (NMOL * NATM)      // 8192
#define NCHUNK 32                // 32-column chunks per row
#define CUTOFF_F 5.2f
#define C2_LO 27.0399f           // sqrtf(C2_LO) <= 5.2f guaranteed
#define C2_HI 27.0401f           // sqrtf(x) > 5.2f for all x > C2_HI guaranteed

__device__ unsigned g_mask[NROWS * NCHUNK];   // 1 MB: hit bitmasks
__device__ int g_rowCnt[NROWS];
__device__ int g_rowOff[NROWS];               // warp-local exclusive offsets
__device__ int g_warpBase[32];                // base per scan-warp (256 rows each)
__device__ int g_total;

__global__ void enum_kernel(const int* __restrict__ species,
                            const float* __restrict__ coords) {
    __shared__ float4 s[NCHUNK];
    const int m = blockIdx.x, rs = blockIdx.y, ck = blockIdx.z;
    const int i = rs * 128 + threadIdx.x;
    const int grow = m * NATM + i;            // flat row id == output i-value
    const int jbase = ck * 32;

    if (jbase + 31 <= rs * 128) {             // no j > i possible: dead tile
        g_mask[grow * NCHUNK + ck] = 0u;
        return;
    }

    const float nanv = __int_as_float(0x7fc00000);

    if (threadIdx.x < 32) {
        const int ga = m * NATM + jbase + threadIdx.x;
        const float* c = coords + (size_t)ga * 3;
        float x = c[0], y = c[1], z = c[2];
        if (species[ga] == -1) { x = nanv; y = nanv; z = nanv; }
        s[threadIdx.x] = make_float4(x, y, z, 0.0f);
    }
    __syncthreads();

    float cx, cy, cz;
    {
        const float* c = coords + (size_t)grow * 3;
        cx = c[0]; cy = c[1]; cz = c[2];
        if (species[grow] == -1) { cx = nanv; cy = nanv; cz = nanv; }
    }

    const int lstart = i + 1 - jbase;         // first valid column in chunk
    unsigned valid = 0xFFFFFFFFu;
    if (lstart > 0) valid = (lstart >= 32) ? 0u : (0xFFFFFFFFu << lstart);

    unsigned mask = 0u;
#pragma unroll
    for (int l = 0; l < 32; l++) {
        float4 cj = s[l];
        float dx = cx - cj.x;
        float dy = cy - cj.y;
        float dz = cz - cj.z;
        float d2 = fmaf(dz, dz, fmaf(dy, dy, dx * dx));
        // NaN compares false -> padded atoms drop out, matching reference.
        bool in = (d2 <= C2_LO) || (d2 <= C2_HI && sqrtf(d2) <= CUTOFF_F);
        mask |= ((unsigned)in) << l;
    }
    g_mask[grow * NCHUNK + ck] = mask & valid;
}

// 256 warps, warp-per-row (32 rows each): coalesced mask load + popc reduce.
__global__ void rowsum_kernel() {
    const int gw = (blockIdx.x * blockDim.x + threadIdx.x) >> 5;
    const int lane = threadIdx.x & 31;
#pragma unroll 4
    for (int it = 0; it < 32; it++) {
        const int row = gw * 32 + it;
        unsigned v = g_mask[row * NCHUNK + lane];
        int sum = __reduce_add_sync(0xFFFFFFFFu, __popc(v));
        if (lane == 0) g_rowCnt[row] = sum;
    }
}

// One block, 1024 threads = 32 warps; warp w scans 256 contiguous rows.
__global__ void scan_kernel() {
    const unsigned FULL = 0xFFFFFFFFu;
    const int w = threadIdx.x >> 5;
    const int lane = threadIdx.x & 31;
    const int base = w * 256;

    int running = 0;
#pragma unroll
    for (int it = 0; it < 8; it++) {
        const int idx = base + it * 32 + lane;
        int v = g_rowCnt[idx];
        int s = v;
#pragma unroll
        for (int off = 1; off < 32; off <<= 1) {
            int t = __shfl_up_sync(FULL, s, off);
            if (lane >= off) s += t;
        }
        g_rowOff[idx] = running + s - v;          // warp-local exclusive
        running += __shfl_sync(FULL, s, 31);
    }

    __shared__ int wt[32];
    if (lane == 0) wt[w] = running;
    __syncthreads();

    if (w == 0) {
        int v = wt[lane];
        int s = v;
#pragma unroll
        for (int off = 1; off < 32; off <<= 1) {
            int t = __shfl_up_sync(FULL, s, off);
            if (lane >= off) s += t;
        }
        g_warpBase[lane] = s - v;
        if (lane == 31) g_total = s;
    }
}

// 256 warps, warp-per-row: lane c = chunk c. popc prefix -> output offsets.
__global__ void emit_kernel(float* __restrict__ out, int out_size) {
    const unsigned FULL = 0xFFFFFFFFu;
    const int gtid = blockIdx.x * blockDim.x + threadIdx.x;
    const int gw = gtid >> 5;
    const int lane = threadIdx.x & 31;
    const int total = g_total;

    for (int it = 0; it < 32; it++) {
        const int row = gw * 32 + it;
        unsigned msk = g_mask[row * NCHUNK + lane];
        int pc = __popc(msk);
        int s = pc;
#pragma unroll
        for (int off = 1; off < 32; off <<= 1) {
            int t = __shfl_up_sync(FULL, s, off);
            if (lane >= off) s += t;
        }
        if (msk) {
            int o = g_rowOff[row] + g_warpBase[row >> 8] + (s - pc);
            const float rowf = (float)row;
            const int jb = (row & ~(NATM - 1)) + lane * 32;
            while (msk) {
                int b = __ffs(msk) - 1;
                msk &= msk - 1;
                out[o] = rowf;
                out[total + o] = (float)(jb + b);
                o++;
            }
        }
    }

    // Zero everything past the 2*P payload (covers the zeros(3) tail).
    const int stride = gridDim.x * blockDim.x;
    for (int idx = gtid; idx < out_size; idx += stride)
        if (idx >= 2 * total) out[idx] = 0.0f;
}

extern "C" void kernel_launch(void* const* d_in, const int* in_sizes, int n_in,
                              void* d_out, int out_size) {
    const int* species = (const int*)d_in[0];
    const float* coords = (const float*)d_in[1];
    float* out = (float*)d_out;

    enum_kernel<<<dim3(NMOL, NATM / 128, NCHUNK), 128>>>(species, coords);
    rowsum_kernel<<<64, 128>>>();
    scan_kernel<<<1, 1024>>>();
    emit_kernel<<<64, 128>>>(out, out_size);
}

// round 8
// speedup vs baseline: 1.4364x; 1.4364x over previous
#include <cuda_runtime.h>
#include <math.h>

// FullPairwise neighbor list: M=8 molecules, N=1024 atoms, cutoff 5.2.
// Output (float32 buffer): [2, P] flat atom indices written as floats
// (row 0: i's, row 1: j's), pairs ordered lexicographically by
// (molecule, i, j); trailing elements (incl. the zeros(3) output) zeroed.
//
// Pipeline:
//  1) enum:   128row x 32col tiles -> one hit-bitmask uint32 per (row,chunk)
//  2) rowsum: warp-per-row popc reduce -> per-row pair counts
//  3) scan:   1-block shfl scan over 8192 row counts (row order == output order)
//  4) emit:   ONE warp per row (8192 warps), popc prefix -> write pairs + tail

#define NMOL 8
#define NATM 1024
#define NROWS (NMOL * NATM)      // 8192
#define NCHUNK 32                // 32-column chunks per row
#define CUTOFF_F 5.2f
#define C2_LO 27.0399f           // sqrtf(C2_LO) <= 5.2f guaranteed
#define C2_HI 27.0401f           // sqrtf(x) > 5.2f for all x > C2_HI guaranteed

__device__ unsigned g_mask[NROWS * NCHUNK];   // 1 MB: hit bitmasks
__device__ int g_rowCnt[NROWS];
__device__ int g_rowOff[NROWS];               // warp-local exclusive offsets
__device__ int g_warpBase[32];                // base per scan-warp (256 rows each)
__device__ int g_total;

__global__ void enum_kernel(const int* __restrict__ species,
                            const float* __restrict__ coords) {
    __shared__ float4 s[NCHUNK];
    const int m = blockIdx.x, rs = blockIdx.y, ck = blockIdx.z;
    const int i = rs * 128 + threadIdx.x;
    const int grow = m * NATM + i;            // flat row id == output i-value
    const int jbase = ck * 32;

    if (jbase + 31 <= rs * 128) {             // no j > i possible: dead tile
        g_mask[grow * NCHUNK + ck] = 0u;
        return;
    }

    const float nanv = __int_as_float(0x7fc00000);

    if (threadIdx.x < 32) {
        const int ga = m * NATM + jbase + threadIdx.x;
        const float* c = coords + (size_t)ga * 3;
        float x = c[0], y = c[1], z = c[2];
        if (species[ga] == -1) { x = nanv; y = nanv; z = nanv; }
        s[threadIdx.x] = make_float4(x, y, z, 0.0f);
    }
    __syncthreads();

    float cx, cy, cz;
    {
        const float* c = coords + (size_t)grow * 3;
        cx = c[0]; cy = c[1]; cz = c[2];
        if (species[grow] == -1) { cx = nanv; cy = nanv; cz = nanv; }
    }

    const int lstart = i + 1 - jbase;         // first valid column in chunk
    unsigned valid = 0xFFFFFFFFu;
    if (lstart > 0) valid = (lstart >= 32) ? 0u : (0xFFFFFFFFu << lstart);

    unsigned mask = 0u;
#pragma unroll
    for (int l = 0; l < 32; l++) {
        float4 cj = s[l];
        float dx = cx - cj.x;
        float dy = cy - cj.y;
        float dz = cz - cj.z;
        float d2 = fmaf(dz, dz, fmaf(dy, dy, dx * dx));
        // NaN compares false -> padded atoms drop out, matching reference.
        bool in = (d2 <= C2_LO) || (d2 <= C2_HI && sqrtf(d2) <= CUTOFF_F);
        mask |= ((unsigned)in) << l;
    }
    g_mask[grow * NCHUNK + ck] = mask & valid;
}

// 256 warps, warp-per-row (32 rows each): coalesced mask load + popc reduce.
__global__ void rowsum_kernel() {
    const int gw = (blockIdx.x * blockDim.x + threadIdx.x) >> 5;
    const int lane = threadIdx.x & 31;
#pragma unroll 4
    for (int it = 0; it < 32; it++) {
        const int row = gw * 32 + it;
        unsigned v = g_mask[row * NCHUNK + lane];
        int sum = __reduce_add_sync(0xFFFFFFFFu, __popc(v));
        if (lane == 0) g_rowCnt[row] = sum;
    }
}

// One block, 1024 threads = 32 warps; warp w scans 256 contiguous rows.
__global__ void scan_kernel() {
    const unsigned FULL = 0xFFFFFFFFu;
    const int w = threadIdx.x >> 5;
    const int lane = threadIdx.x & 31;
    const int base = w * 256;

    int running = 0;
#pragma unroll
    for (int it = 0; it < 8; it++) {
        const int idx = base + it * 32 + lane;
        int v = g_rowCnt[idx];
        int s = v;
#pragma unroll
        for (int off = 1; off < 32; off <<= 1) {
            int t = __shfl_up_sync(FULL, s, off);
            if (lane >= off) s += t;
        }
        g_rowOff[idx] = running + s - v;          // warp-local exclusive
        running += __shfl_sync(FULL, s, 31);
    }

    __shared__ int wt[32];
    if (lane == 0) wt[w] = running;
    __syncthreads();

    if (w == 0) {
        int v = wt[lane];
        int s = v;
#pragma unroll
        for (int off = 1; off < 32; off <<= 1) {
            int t = __shfl_up_sync(FULL, s, off);
            if (lane >= off) s += t;
        }
        g_warpBase[lane] = s - v;
        if (lane == 31) g_total = s;
    }
}

// ONE warp per row: lane c = chunk c. popc prefix -> output offsets.
// 2048 blocks x 128 threads = 8192 warps, high occupancy, no outer loop.
__global__ void emit_kernel(float* __restrict__ out, int out_size) {
    const unsigned FULL = 0xFFFFFFFFu;
    const int gtid = blockIdx.x * blockDim.x + threadIdx.x;
    const int row = gtid >> 5;                // global warp id == row
    const int lane = threadIdx.x & 31;
    const int total = g_total;

    unsigned msk = g_mask[row * NCHUNK + lane];
    int pc = __popc(msk);
    int s = pc;
#pragma unroll
    for (int off = 1; off < 32; off <<= 1) {
        int t = __shfl_up_sync(FULL, s, off);
        if (lane >= off) s += t;
    }
    if (msk) {
        int o = g_rowOff[row] + g_warpBase[row >> 8] + (s - pc);
        const float rowf = (float)row;
        const int jb = (row & ~(NATM - 1)) + lane * 32;
        while (msk) {
            int b = __ffs(msk) - 1;
            msk &= msk - 1;
            out[o] = rowf;
            out[total + o] = (float)(jb + b);
            o++;
        }
    }

    // Zero everything past the 2*P payload (covers the zeros(3) tail).
    // 262144 threads >= out_size, so this is one strided step.
    const int stride = gridDim.x * blockDim.x;
    for (int idx = gtid; idx < out_size; idx += stride)
        if (idx >= 2 * total) out[idx] = 0.0f;
}

extern "C" void kernel_launch(void* const* d_in, const int* in_sizes, int n_in,
                              void* d_out, int out_size) {
    const int* species = (const int*)d_in[0];
    const float* coords = (const float*)d_in[1];
    float* out = (float*)d_out;

    enum_kernel<<<dim3(NMOL, NATM / 128, NCHUNK), 128>>>(species, coords);
    rowsum_kernel<<<64, 128>>>();
    scan_kernel<<<1, 1024>>>();
    emit_kernel<<<NROWS * 32 / 128, 128>>>(out, out_size);
}

// round 9
// speedup vs baseline: 3.0846x; 2.1475x over previous
#include <cuda_runtime.h>
#include <math.h>

// FullPairwise neighbor list: M=8 molecules, N=1024 atoms, cutoff 5.2.
// Output (float32 buffer): [2, P] flat atom indices written as floats
// (row 0: i's, row 1: j's), pairs ordered lexicographically by
// (molecule, i, j); trailing elements (incl. the zeros(3) output) zeroed.
//
// SINGLE persistent kernel, 256 all-resident blocks + software grid barrier:
//   A) block = 32 rows (warp=row, lane=32-col chunk); molecule coords in
//      padded smem; per-lane hit bitmask stays in registers; block-local
//      row scan -> g_blkSum[block]
//   B) grid barrier (monotonic epoch, graph-replay safe); every block
//      redundantly prefix-sums the 256 block totals
//   C) emit pairs from register masks + zero the tail.

#define NMOL 8
#define NATM 1024
#define NROWS 8192
#define NBLK 256
#define NTHR 1024
#define CUTOFF_F 5.2f
#define C2_LO 27.0399f           // sqrtf(C2_LO) <= 5.2f guaranteed
#define C2_HI 27.0401f           // sqrtf(x) > 5.2f for all x > C2_HI guaranteed

__device__ int g_blkSum[NBLK];
__device__ unsigned g_arrive;    // monotonic across launches (zero-init once)
__device__ unsigned g_epoch;     // incremented by last arrival of each launch

__global__ void __launch_bounds__(NTHR, 2)
fused_kernel(const int* __restrict__ species,
             const float* __restrict__ coords,
             float* __restrict__ out, int out_size) {
    __shared__ float2 sxy[1056];      // +1-per-32 padded: idx = a + (a>>5)
    __shared__ float  sz[1056];
    __shared__ int s_rowCnt[32];
    __shared__ int s_rowOff[32];
    __shared__ int s_base2[2];        // [0]=blockBase, [1]=grandTotal

    const unsigned FULL = 0xFFFFFFFFu;
    const int b = blockIdx.x;
    const int tid = threadIdx.x;
    const int w = tid >> 5;           // warp = row-in-block
    const int c = tid & 31;           // lane = chunk

    const int grow = b * 32 + w;      // global flat row == output i value
    const int mb = grow & ~(NATM - 1);
    const int iloc = grow & (NATM - 1);

    // ---- stage molecule coords (NaN-fill padded atoms) ----
    {
        const int ga = mb + tid;
        const float* cp = coords + (size_t)ga * 3;
        float x = cp[0], y = cp[1], z = cp[2];
        if (species[ga] == -1) {
            const float nanv = __int_as_float(0x7fc00000);
            x = nanv; y = nanv; z = nanv;
        }
        const int p = tid + (tid >> 5);
        sxy[p] = make_float2(x, y);
        sz[p] = z;
    }
    __syncthreads();

    // ---- my row coordinate ----
    const int ip = iloc + (iloc >> 5);
    const float2 cxy = sxy[ip];
    const float cz = sz[ip];

    // j > i validity within my chunk
    const int lstart = iloc + 1 - c * 32;
    unsigned valid = 0xFFFFFFFFu;
    if (lstart > 0) valid = (lstart >= 32) ? 0u : (0xFFFFFFFFu << lstart);

    // ---- phase A: 32 pair tests -> bitmask (stays in registers) ----
    unsigned mask = 0u;
    const int sbase = c * 33;         // padded base of my chunk
#pragma unroll 8
    for (int l = 0; l < 32; l++) {
        float2 j2 = sxy[sbase + l];
        float jz = sz[sbase + l];
        float dx = cxy.x - j2.x;
        float dy = cxy.y - j2.y;
        float dz = cz - jz;
        float d2 = fmaf(dz, dz, fmaf(dy, dy, dx * dx));
        // NaN compares false -> padded atoms drop out (matches reference)
        bool in = (d2 <= C2_LO) || (d2 <= C2_HI && sqrtf(d2) <= CUTOFF_F);
        mask |= ((unsigned)in) << l;
    }
    mask &= valid;

    // ---- per-row counts + block-local exclusive row offsets ----
    const int pc = __popc(mask);
    const int rsum = __reduce_add_sync(FULL, pc);
    if (c == 0) s_rowCnt[w] = rsum;
    __syncthreads();
    if (w == 0) {
        int v = s_rowCnt[c];
        int s = v;
#pragma unroll
        for (int off = 1; off < 32; off <<= 1) {
            int t = __shfl_up_sync(FULL, s, off);
            if (c >= off) s += t;
        }
        s_rowOff[c] = s - v;
        if (c == 31) {
            g_blkSum[b] = s;          // block total
            __threadfence();          // make visible before barrier arrive
        }
    }
    __syncthreads();

    // ---- grid barrier (monotonic epoch: safe across graph replays) ----
    if (tid == 0) {
        unsigned my = atomicAdd(&g_arrive, 1);
        unsigned target = my + 1;
        if ((target & (NBLK - 1)) == 0u)   // last arrival of this launch
            atomicAdd(&g_epoch, 1);
        while ((int)(NBLK * (*(volatile unsigned*)&g_epoch) - target) < 0)
            __nanosleep(32);
        __threadfence();
    }
    __syncthreads();

    // ---- phase B: redundant prefix over 256 block totals ----
    if (w == 0) {
        int bsum = 0, tsum = 0;
#pragma unroll
        for (int q = 0; q < NBLK / 32; q++) {
            const int k = q * 32 + c;
            const int v = __ldcg(&g_blkSum[k]);
            tsum += v;
            if (k < b) bsum += v;
        }
        bsum = __reduce_add_sync(FULL, bsum);
        tsum = __reduce_add_sync(FULL, tsum);
        if (c == 0) { s_base2[0] = bsum; s_base2[1] = tsum; }
    }
    __syncthreads();

    // ---- phase C: emit pairs ----
    const int blockBase = s_base2[0];
    const int total = s_base2[1];
    {
        int s = pc;
#pragma unroll
        for (int off = 1; off < 32; off <<= 1) {
            int t = __shfl_up_sync(FULL, s, off);
            if (c >= off) s += t;
        }
        int o = blockBase + s_rowOff[w] + (s - pc);
        if (mask) {
            const float rowf = (float)grow;
            const int jb = mb + c * 32;
            unsigned mm = mask;
            while (mm) {
                const int l = __ffs(mm) - 1;
                mm &= mm - 1;
                out[o] = rowf;
                out[total + o] = (float)(jb + l);
                o++;
            }
        }
    }

    // ---- tail: zero past the 2*P payload (covers the zeros(3) output) ----
    const int gtid = b * NTHR + tid;
    for (int idx = gtid; idx < out_size; idx += NBLK * NTHR)
        if (idx >= 2 * total) out[idx] = 0.0f;
}

extern "C" void kernel_launch(void* const* d_in, const int* in_sizes, int n_in,
                              void* d_out, int out_size) {
    const int* species = (const int*)d_in[0];
    const float* coords = (const float*)d_in[1];
    float* out = (float*)d_out;

    fused_kernel<<<NBLK, NTHR>>>(species, coords, out, out_size);
}

// round 10
// speedup vs baseline: 3.1741x; 1.0290x over previous
#include <cuda_runtime.h>
#include <math.h>

// FullPairwise neighbor list: M=8 molecules, N=1024 atoms, cutoff 5.2.
// Output (float32 buffer): [2, P] flat atom indices written as floats
// (row 0: i's, row 1: j's), pairs ordered lexicographically by
// (molecule, i, j); trailing elements (incl. the zeros(3) output) zeroed.
//
// SINGLE persistent kernel, 256 all-resident blocks + software grid barrier.
// Cutoff test: sqrtf is correctly rounded & monotone, so
//   sqrtf(d2) <= 5.2f  <=>  d2 <= 27.039999008178710938f (0x41D851EB)
// exactly, for every finite f32 d2 (NaN -> false). Single FSETP, no MUFU.

#define NMOL 8
#define NATM 1024
#define NROWS 8192
#define NBLK 256
#define NTHR 1024
#define C2_EXACT 27.039999008178710938f   // largest f32 with sqrtf(x) <= 5.2f

__device__ int g_blkSum[NBLK];
__device__ unsigned g_arrive;    // monotonic across launches (zero-init once)
__device__ unsigned g_epoch;     // incremented by last arrival of each launch

__global__ void __launch_bounds__(NTHR, 2)
fused_kernel(const int* __restrict__ species,
             const float* __restrict__ coords,
             float* __restrict__ out, int out_size) {
    __shared__ float4 s4[1056];       // +1-per-32 padded: idx = a + (a>>5)
    __shared__ int s_rowCnt[32];
    __shared__ int s_rowOff[32];
    __shared__ int s_base2[2];        // [0]=blockBase, [1]=grandTotal

    const unsigned FULL = 0xFFFFFFFFu;
    const int b = blockIdx.x;
    const int tid = threadIdx.x;
    const int w = tid >> 5;           // warp = row-in-block
    const int c = tid & 31;           // lane = chunk

    const int grow = b * 32 + w;      // global flat row == output i value
    const int mb = grow & ~(NATM - 1);
    const int iloc = grow & (NATM - 1);

    // ---- stage molecule coords (NaN-fill padded atoms) ----
    {
        const int ga = mb + tid;
        const float* cp = coords + (size_t)ga * 3;
        float x = cp[0], y = cp[1], z = cp[2];
        if (species[ga] == -1) {
            const float nanv = __int_as_float(0x7fc00000);
            x = nanv; y = nanv; z = nanv;
        }
        s4[tid + (tid >> 5)] = make_float4(x, y, z, 0.0f);
    }
    __syncthreads();

    // ---- my row coordinate ----
    const float4 ci = s4[iloc + (iloc >> 5)];

    // j > i validity within my chunk
    const int lstart = iloc + 1 - c * 32;
    unsigned valid = 0xFFFFFFFFu;
    if (lstart > 0) valid = (lstart >= 32) ? 0u : (0xFFFFFFFFu << lstart);

    // ---- phase A: 32 pair tests -> bitmask (stays in registers) ----
    // LDS.128 at chunk stride 33*16B: each 8-lane phase covers all 32 banks
    // exactly once -> conflict-free at the structural 4-wavefront floor.
    unsigned mask = 0u;
    const int sbase = c * 33;
#pragma unroll 8
    for (int l = 0; l < 32; l++) {
        float4 cj = s4[sbase + l];
        float dx = ci.x - cj.x;
        float dy = ci.y - cj.y;
        float dz = ci.z - cj.z;
        float d2 = fmaf(dz, dz, fmaf(dy, dy, dx * dx));
        bool in = d2 <= C2_EXACT;     // exact sqrtf(d2)<=5.2f; NaN -> false
        mask |= ((unsigned)in) << l;
    }
    mask &= valid;

    // ---- per-row counts + block-local exclusive row offsets ----
    const int pc = __popc(mask);
    const int rsum = __reduce_add_sync(FULL, pc);
    if (c == 0) s_rowCnt[w] = rsum;
    __syncthreads();
    if (w == 0) {
        int v = s_rowCnt[c];
        int s = v;
#pragma unroll
        for (int off = 1; off < 32; off <<= 1) {
            int t = __shfl_up_sync(FULL, s, off);
            if (c >= off) s += t;
        }
        s_rowOff[c] = s - v;
        if (c == 31) {
            g_blkSum[b] = s;          // block total
            __threadfence();          // make visible before barrier arrive
        }
    }
    __syncthreads();

    // ---- grid barrier (monotonic epoch: safe across graph replays) ----
    if (tid == 0) {
        unsigned my = atomicAdd(&g_arrive, 1);
        unsigned target = my + 1;
        if ((target & (NBLK - 1)) == 0u)   // last arrival of this launch
            atomicAdd(&g_epoch, 1);
        while ((int)(NBLK * (*(volatile unsigned*)&g_epoch) - target) < 0)
            __nanosleep(32);
        __threadfence();
    }
    __syncthreads();

    // ---- phase B: redundant prefix over 256 block totals ----
    if (w == 0) {
        int bsum = 0, tsum = 0;
#pragma unroll
        for (int q = 0; q < NBLK / 32; q++) {
            const int k = q * 32 + c;
            const int v = __ldcg(&g_blkSum[k]);
            tsum += v;
            if (k < b) bsum += v;
        }
        bsum = __reduce_add_sync(FULL, bsum);
        tsum = __reduce_add_sync(FULL, tsum);
        if (c == 0) { s_base2[0] = bsum; s_base2[1] = tsum; }
    }
    __syncthreads();

    // ---- phase C: emit pairs ----
    const int blockBase = s_base2[0];
    const int total = s_base2[1];
    {
        int s = pc;
#pragma unroll
        for (int off = 1; off < 32; off <<= 1) {
            int t = __shfl_up_sync(FULL, s, off);
            if (c >= off) s += t;
        }
        int o = blockBase + s_rowOff[w] + (s - pc);
        if (mask) {
            const float rowf = (float)grow;
            const int jb = mb + c * 32;
            unsigned mm = mask;
            while (mm) {
                const int l = __ffs(mm) - 1;
                mm &= mm - 1;
                out[o] = rowf;
                out[total + o] = (float)(jb + l);
                o++;
            }
        }
    }

    // ---- tail: zero past the 2*P payload (covers the zeros(3) output) ----
    const int gtid = b * NTHR + tid;
    for (int idx = gtid; idx < out_size; idx += NBLK * NTHR)
        if (idx >= 2 * total) out[idx] = 0.0f;
}

extern "C" void kernel_launch(void* const* d_in, const int* in_sizes, int n_in,
                              void* d_out, int out_size) {
    const int* species = (const int*)d_in[0];
    const float* coords = (const float*)d_in[1];
    float* out = (float*)d_out;

    fused_kernel<<<NBLK, NTHR>>>(species, coords, out, out_size);
}

// round 11
// speedup vs baseline: 3.5285x; 1.1117x over previous
#include <cuda_runtime.h>
#include <math.h>

// FullPairwise neighbor list: M=8 molecules, N=1024 atoms, cutoff 5.2.
// Output (float32 buffer): [2, P] flat atom indices written as floats
// (row 0: i's, row 1: j's), pairs ordered lexicographically by
// (molecule, i, j); trailing elements (incl. the zeros(3) output) zeroed.
//
// SINGLE persistent kernel, 256 all-resident blocks + software grid barrier.
// 2-row register blocking: 512 threads = 16 warps x 2 rows; each LDS.128 of a
// j-atom serves two pair tests -> smem wavefront traffic halved vs 1 row/warp.
// Cutoff: sqrtf is correctly rounded & monotone, so sqrtf(d2) <= 5.2f
//   <=>  d2 <= 27.039999008178710938f (0x41D851EB) exactly (NaN -> false).

#define NMOL 8
#define NATM 1024
#define NROWS 8192
#define NBLK 256
#define NTHR 512
#define C2_EXACT 27.039999008178710938f   // largest f32 with sqrtf(x) <= 5.2f

__device__ int g_blkSum[NBLK];
__device__ unsigned g_arrive;    // monotonic across launches (zero-init once)
__device__ unsigned g_epoch;     // incremented by last arrival of each launch

__device__ __forceinline__ unsigned valid_mask(int iloc, int c) {
    const int ls = iloc + 1 - c * 32;     // first j > i within chunk c
    if (ls <= 0) return 0xFFFFFFFFu;
    return (ls >= 32) ? 0u : (0xFFFFFFFFu << ls);
}

__global__ void __launch_bounds__(NTHR, 2)
fused_kernel(const int* __restrict__ species,
             const float* __restrict__ coords,
             float* __restrict__ out, int out_size) {
    __shared__ float4 s4[1056];       // +1-per-32 padded: idx = a + (a>>5)
    __shared__ int s_rowCnt[32];
    __shared__ int s_rowOff[32];
    __shared__ int s_base2[2];        // [0]=blockBase, [1]=grandTotal

    const unsigned FULL = 0xFFFFFFFFu;
    const int b = blockIdx.x;
    const int tid = threadIdx.x;
    const int w = tid >> 5;           // warp 0..15, handles rows 2w, 2w+1
    const int c = tid & 31;           // lane = chunk

    const int grow0 = b * 32 + 2 * w; // global flat rows (== output i values)
    const int mb = grow0 & ~(NATM - 1);
    const int iloc0 = grow0 & (NATM - 1);
    const int iloc1 = iloc0 + 1;

    // ---- stage molecule coords (NaN-fill padded atoms) ----
    for (int a = tid; a < NATM; a += NTHR) {
        const int ga = mb + a;
        const float* cp = coords + (size_t)ga * 3;
        float x = cp[0], y = cp[1], z = cp[2];
        if (species[ga] == -1) {
            const float nanv = __int_as_float(0x7fc00000);
            x = nanv; y = nanv; z = nanv;
        }
        s4[a + (a >> 5)] = make_float4(x, y, z, 0.0f);
    }
    __syncthreads();

    // ---- my two row coordinates ----
    const float4 ci0 = s4[iloc0 + (iloc0 >> 5)];
    const float4 ci1 = s4[iloc1 + (iloc1 >> 5)];
    const unsigned valid0 = valid_mask(iloc0, c);
    const unsigned valid1 = valid_mask(iloc1, c);

    // ---- phase A: 32 LDS.128, 64 pair tests -> two register bitmasks ----
    unsigned mask0 = 0u, mask1 = 0u;
    const int sbase = c * 33;         // padded chunk base (conflict-free)
#pragma unroll 4
    for (int l = 0; l < 32; l++) {
        const float4 cj = s4[sbase + l];
        {
            float dx = ci0.x - cj.x, dy = ci0.y - cj.y, dz = ci0.z - cj.z;
            float d2 = fmaf(dz, dz, fmaf(dy, dy, dx * dx));
            mask0 |= ((unsigned)(d2 <= C2_EXACT)) << l;   // NaN -> false
        }
        {
            float dx = ci1.x - cj.x, dy = ci1.y - cj.y, dz = ci1.z - cj.z;
            float d2 = fmaf(dz, dz, fmaf(dy, dy, dx * dx));
            mask1 |= ((unsigned)(d2 <= C2_EXACT)) << l;
        }
    }
    mask0 &= valid0;
    mask1 &= valid1;

    // ---- per-row counts + block-local exclusive row offsets ----
    const int pc0 = __popc(mask0);
    const int pc1 = __popc(mask1);
    const int rs0 = __reduce_add_sync(FULL, pc0);
    const int rs1 = __reduce_add_sync(FULL, pc1);
    if (c == 0) { s_rowCnt[2 * w] = rs0; s_rowCnt[2 * w + 1] = rs1; }
    __syncthreads();
    if (w == 0) {
        int v = s_rowCnt[c];
        int s = v;
#pragma unroll
        for (int off = 1; off < 32; off <<= 1) {
            int t = __shfl_up_sync(FULL, s, off);
            if (c >= off) s += t;
        }
        s_rowOff[c] = s - v;
        if (c == 31) {
            g_blkSum[b] = s;          // block total
            __threadfence();          // visible before barrier arrive
        }
    }
    __syncthreads();

    // ---- grid barrier (monotonic epoch: safe across graph replays) ----
    if (tid == 0) {
        unsigned my = atomicAdd(&g_arrive, 1);
        unsigned target = my + 1;
        if ((target & (NBLK - 1)) == 0u)   // last arrival of this launch
            atomicAdd(&g_epoch, 1);
        while ((int)(NBLK * (*(volatile unsigned*)&g_epoch) - target) < 0)
            __nanosleep(32);
        __threadfence();
    }
    __syncthreads();

    // ---- phase B: redundant prefix over 256 block totals ----
    if (w == 0) {
        int bsum = 0, tsum = 0;
#pragma unroll
        for (int q = 0; q < NBLK / 32; q++) {
            const int k = q * 32 + c;
            const int v = __ldcg(&g_blkSum[k]);
            tsum += v;
            if (k < b) bsum += v;
        }
        bsum = __reduce_add_sync(FULL, bsum);
        tsum = __reduce_add_sync(FULL, tsum);
        if (c == 0) { s_base2[0] = bsum; s_base2[1] = tsum; }
    }
    __syncthreads();

    // ---- phase C: emit pairs (two rows per warp) ----
    const int blockBase = s_base2[0];
    const int total = s_base2[1];
    const int jb = mb + c * 32;
    {   // row 0
        int s = pc0;
#pragma unroll
        for (int off = 1; off < 32; off <<= 1) {
            int t = __shfl_up_sync(FULL, s, off);
            if (c >= off) s += t;
        }
        int o = blockBase + s_rowOff[2 * w] + (s - pc0);
        if (mask0) {
            const float rowf = (float)grow0;
            unsigned mm = mask0;
            while (mm) {
                const int l = __ffs(mm) - 1;
                mm &= mm - 1;
                out[o] = rowf;
                out[total + o] = (float)(jb + l);
                o++;
            }
        }
    }
    {   // row 1
        int s = pc1;
#pragma unroll
        for (int off = 1; off < 32; off <<= 1) {
            int t = __shfl_up_sync(FULL, s, off);
            if (c >= off) s += t;
        }
        int o = blockBase + s_rowOff[2 * w + 1] + (s - pc1);
        if (mask1) {
            const float rowf = (float)(grow0 + 1);
            unsigned mm = mask1;
            while (mm) {
                const int l = __ffs(mm) - 1;
                mm &= mm - 1;
                out[o] = rowf;
                out[total + o] = (float)(jb + l);
                o++;
            }
        }
    }

    // ---- tail: zero past the 2*P payload (covers the zeros(3) output) ----
    const int gtid = b * NTHR + tid;
    for (int idx = gtid; idx < out_size; idx += NBLK * NTHR)
        if (idx >= 2 * total) out[idx] = 0.0f;
}

extern "C" void kernel_launch(void* const* d_in, const int* in_sizes, int n_in,
                              void* d_out, int out_size) {
    const int* species = (const int*)d_in[0];
    const float* coords = (const float*)d_in[1];
    float* out = (float*)d_out;

    fused_kernel<<<NBLK, NTHR>>>(species, coords, out, out_size);
}